// round 16
// baseline (speedup 1.0000x reference)
#include <cuda_runtime.h>
#include <math.h>

// ---------------- problem constants ----------------
#define B_      1024
#define T_      256
#define DIN_    128
#define INTER_  269
#define CMD_    179
#define MOTOR_  64
#define OUT_    64
#define UNITS_  512
#define CAT0    397
#define CAT1    448
#define CAT2    243

#define MBT     16                 // batch rows per team (cluster of 2)
#define NBLK    128                // 64 teams x 2
#define NTHR    768                // 24 warps (6/SMSP)
#define PSTR    52                 // partial slot stride (floats, 16B aligned)

// X rows: [h0 | h1 | h2]; each row = 16 batch floats.
#define XR_H0   0
#define XR_H1   269
#define XR_H2   448
#define XROWS   512

#define KC0     5                  // 135*5=675 tasks (k-range 269)
#define KC1     8                  // 90*8=720
#define KC2     24                 // 32*24=768

#define P0_ (CAT0 * INTER_)
#define P1_ (CAT1 * CMD_)
#define P2_ (CAT2 * MOTOR_)
#define PTOT_ (P0_ + P1_ + P2_)

#define BT_     (B_ * T_)
#define PXN     ((size_t)BT_ * INTER_ * 3)

// ---------------- device scratch ----------------
__device__ __align__(16) float4 g_wq0[P0_];
__device__ __align__(16) float4 g_wq1[P1_];
__device__ __align__(16) float4 g_wq2[P2_];
__device__ float g_px[PXN];          // precomputed x_t @ Wx for layer 0

struct Params {
    const float* x;
    const float* hidden;
    const void*  mask0;
    const void*  mask1;
    const void*  mask2;
    const float* w0[4]; const float* b0[4];   // ff1, ff2, ta, tb
    const float* w1[4]; const float* b1[4];
    const float* w2[4]; const float* b2[4];
    const float* fc_w;  const float* fc_b;
    float* out;
};

// ---------------- mask helper ----------------
__device__ __forceinline__ float mask_val(const void* mp, int mode, int e) {
    if (mode == 0) return ((const unsigned char*)mp)[e] ? 1.0f : 0.0f;
    if (mode == 1) return ((const int*)mp)[e] ? 1.0f : 0.0f;
    return (((const float*)mp)[e] != 0.0f) ? 1.0f : 0.0f;
}

// ---------------- prep: sniff mask dtype + folded/masked/transposed float4 weights ----------------
__global__ void prep_kernel(Params P) {
    __shared__ int smode[3];
    {
        int w = threadIdx.x >> 5, lane = threadIdx.x & 31;
        if (w < 3) {
            const unsigned char* p = (const unsigned char*)
                (w == 0 ? P.mask0 : (w == 1 ? P.mask1 : P.mask2));
            int nz = 0, gt = 0;
            for (int i = lane; i < 4096; i += 32) {
                unsigned char v = p[i];
                nz += (v != 0);
                gt |= (v > 1);
            }
            nz = __reduce_add_sync(0xffffffffu, nz);
            gt = __reduce_or_sync(0xffffffffu, gt);
            if (lane == 0) smode[w] = gt ? 2 : (nz > 2048 ? 0 : 1);
        }
    }
    __syncthreads();

    int p = blockIdx.x * blockDim.x + threadIdx.x;
    if (p >= PTOT_) return;

    int NH, CATL, local, mode;
    float4* wq;
    const float* const* ws;
    const void* mp;
    if (p < P0_) {
        local = p; NH = INTER_; CATL = CAT0;
        wq = g_wq0; ws = P.w0; mp = P.mask0; mode = smode[0];
    } else if (p < P0_ + P1_) {
        local = p - P0_; NH = CMD_; CATL = CAT1;
        wq = g_wq1; ws = P.w1; mp = P.mask1; mode = smode[1];
    } else {
        local = p - P0_ - P1_; NH = MOTOR_; CATL = CAT2;
        wq = g_wq2; ws = P.w2; mp = P.mask2; mode = smode[2];
    }
    int k = local / NH;
    int j = local - k * NH;
    int we = j * CATL + k;
    float m = mask_val(mp, mode, we);
    float4 v;
    v.x = ws[0][we] * m;
    v.y = ws[1][we] * m;
    v.z = ws[2][we] + ws[3][we];
    v.w = 0.0f;
    wq[local] = v;
}

// ---------------- asm helpers ----------------
__device__ __forceinline__ unsigned long long pack2(float w) {
    unsigned long long r;
    asm("mov.b64 %0, {%1, %1};" : "=l"(r) : "f"(w));
    return r;
}
#define FFMA2(acc, w2, x2) \
    asm("fma.rn.f32x2 %0, %1, %2, %0;" : "+l"(acc) : "l"(w2), "l"(x2))

__device__ __forceinline__ float2 unpack2(unsigned long long v) {
    float2 r;
    asm("mov.b64 {%0, %1}, %2;" : "=f"(r.x), "=f"(r.y) : "l"(v));
    return r;
}
__device__ __forceinline__ unsigned s2u(const void* p) {
    unsigned a;
    asm("{ .reg .u64 t; cvta.to.shared.u64 t, %1; cvt.u32.u64 %0, t; }"
        : "=r"(a) : "l"(p));
    return a;
}
__device__ __forceinline__ void st_peer(unsigned laddr, int peer, float v) {
    unsigned ra;
    asm("mapa.shared::cluster.u32 %0, %1, %2;" : "=r"(ra) : "r"(laddr), "r"(peer));
    asm volatile("st.shared::cluster.f32 [%0], %1;" :: "r"(ra), "f"(v) : "memory");
}
__device__ __forceinline__ unsigned my_rank() {
    unsigned r; asm("mov.u32 %0, %%cluster_ctarank;" : "=r"(r)); return r;
}
#define CLUSTER_ARRIVE() asm volatile("barrier.cluster.arrive.aligned;" ::: "memory")
#define CLUSTER_WAIT()   asm volatile("barrier.cluster.wait.aligned;" ::: "memory")

// ---------------- precompute: px[bt][j][0..2] = sum_k x[bt][k] * wx[g][j][k] ----------------
__global__ void __launch_bounds__(640) precomp_kernel(const float* __restrict__ x) {
    __shared__ float xs[128 * 20];
    const int tid = threadIdx.x;
    const int bt0 = blockIdx.x * 16;

    for (int q = tid; q < 16 * 128; q += 640) {
        int m = q >> 7, k = q & 127;
        xs[k * 20 + m] = x[(size_t)(bt0 + m) * DIN_ + k];
    }
    __syncthreads();

    if (tid < 2 * INTER_) {
        int mc = tid / INTER_;
        int jl = tid - mc * INTER_;
        const float4* wp = g_wq0 + jl;      // rows k=0..127 are the x-part
        unsigned long long a[12];
#pragma unroll
        for (int i = 0; i < 12; ++i) a[i] = 0ULL;

        float4 wv = __ldg(wp); wp += INTER_;
#pragma unroll 2
        for (int k = 0; k < 127; ++k) {
            float4 wn = __ldg(wp); wp += INTER_;
            const float* xb = xs + k * 20 + mc * 8;
            ulonglong2 x01 = *(const ulonglong2*)xb;
            ulonglong2 x23 = *(const ulonglong2*)(xb + 4);
            unsigned long long p1 = pack2(wv.x);
            unsigned long long p2 = pack2(wv.y);
            unsigned long long p3 = pack2(wv.z);
            FFMA2(a[0], p1, x01.x); FFMA2(a[1], p1, x01.y);
            FFMA2(a[2], p1, x23.x); FFMA2(a[3], p1, x23.y);
            FFMA2(a[4], p2, x01.x); FFMA2(a[5], p2, x01.y);
            FFMA2(a[6], p2, x23.x); FFMA2(a[7], p2, x23.y);
            FFMA2(a[8], p3, x01.x); FFMA2(a[9], p3, x01.y);
            FFMA2(a[10], p3, x23.x); FFMA2(a[11], p3, x23.y);
            wv = wn;
        }
        {   // k = 127
            const float* xb = xs + 127 * 20 + mc * 8;
            ulonglong2 x01 = *(const ulonglong2*)xb;
            ulonglong2 x23 = *(const ulonglong2*)(xb + 4);
            unsigned long long p1 = pack2(wv.x);
            unsigned long long p2 = pack2(wv.y);
            unsigned long long p3 = pack2(wv.z);
            FFMA2(a[0], p1, x01.x); FFMA2(a[1], p1, x01.y);
            FFMA2(a[2], p1, x23.x); FFMA2(a[3], p1, x23.y);
            FFMA2(a[4], p2, x01.x); FFMA2(a[5], p2, x01.y);
            FFMA2(a[6], p2, x23.x); FFMA2(a[7], p2, x23.y);
            FFMA2(a[8], p3, x01.x); FFMA2(a[9], p3, x01.y);
            FFMA2(a[10], p3, x23.x); FFMA2(a[11], p3, x23.y);
        }
#pragma unroll
        for (int g = 0; g < 3; ++g)
#pragma unroll
            for (int q = 0; q < 4; ++q) {
                float2 v = unpack2(a[g * 4 + q]);
                size_t m0 = (size_t)(bt0 + mc * 8 + 2 * q);
                g_px[(m0 * INTER_ + jl) * 3 + g] = v.x;
                g_px[((m0 + 1) * INTER_ + jl) * 3 + g] = v.y;
            }
    }
}

// ---------------- 24-acc FMA body ----------------
#define FMA_BODY(wv, xp)                                                     \
    do {                                                                     \
        ulonglong2 x01 = *(const ulonglong2*)(xp);                           \
        ulonglong2 x23 = *(const ulonglong2*)((xp) + 4);                     \
        ulonglong2 x45 = *(const ulonglong2*)((xp) + 8);                     \
        ulonglong2 x67 = *(const ulonglong2*)((xp) + 12);                    \
        unsigned long long p1 = pack2((wv).x);                               \
        unsigned long long p2 = pack2((wv).y);                               \
        unsigned long long p3 = pack2((wv).z);                               \
        FFMA2(a[0],  p1, x01.x); FFMA2(a[1],  p1, x01.y);                    \
        FFMA2(a[2],  p1, x23.x); FFMA2(a[3],  p1, x23.y);                    \
        FFMA2(a[4],  p1, x45.x); FFMA2(a[5],  p1, x45.y);                    \
        FFMA2(a[6],  p1, x67.x); FFMA2(a[7],  p1, x67.y);                    \
        FFMA2(a[8],  p2, x01.x); FFMA2(a[9],  p2, x01.y);                    \
        FFMA2(a[10], p2, x23.x); FFMA2(a[11], p2, x23.y);                    \
        FFMA2(a[12], p2, x45.x); FFMA2(a[13], p2, x45.y);                    \
        FFMA2(a[14], p2, x67.x); FFMA2(a[15], p2, x67.y);                    \
        FFMA2(a[16], p3, x01.x); FFMA2(a[17], p3, x01.y);                    \
        FFMA2(a[18], p3, x23.x); FFMA2(a[19], p3, x23.y);                    \
        FFMA2(a[20], p3, x45.x); FFMA2(a[21], p3, x45.y);                    \
        FFMA2(a[22], p3, x67.x); FFMA2(a[23], p3, x67.y);                    \
    } while (0)

// ---------------- one layer ----------------
// pxBase (PX only): g_px slice for this step; element addr = pxBase + b*T*INTER*3 + j*3
template <int KRANGE, int NHW, int KC, int XOFF, int HOFF, int UMAX, bool PX>
__device__ __forceinline__ void do_layer(const float4* __restrict__ wq,
                                         const float* __restrict__ bb,
                                         float* __restrict__ X,
                                         float* __restrict__ part,
                                         const float* __restrict__ pxBase,
                                         int jbase, int jlc, int peer, int tid) {
    const int kc = tid / jlc;
    const int jl = tid - kc * jlc;
    if (kc < KC) {
        const int ka = (KRANGE * kc) / KC;
        const int kb = (KRANGE * (kc + 1)) / KC;
        const float4* wp = wq + (size_t)ka * NHW + jbase + jl;
        const float* xp = X + (size_t)(XOFF + ka) * MBT;

        unsigned long long a[24];
#pragma unroll
        for (int i = 0; i < 24; ++i) a[i] = 0ULL;

        // depth-1 rolling weight prefetch (covered by 6-warp issue wall)
        float4 wv = __ldg(wp); wp += NHW;
#pragma unroll 2
        for (int k = ka; k < kb - 1; ++k) {
            float4 wn = __ldg(wp); wp += NHW;
            FMA_BODY(wv, xp);
            xp += MBT;
            wv = wn;
        }
        FMA_BODY(wv, xp);

        float* pp = part + tid * PSTR;
#pragma unroll
        for (int g = 0; g < 3; ++g)
#pragma unroll
            for (int q = 0; q < 4; ++q) {
                ulonglong2 s;
                s.x = a[g * 8 + q * 2];
                s.y = a[g * 8 + q * 2 + 1];
                *(ulonglong2*)(pp + g * 16 + q * 4) = s;
            }
    }
    __syncthreads();          // partials visible; local X reads done
    CLUSTER_ARRIVE();         // publish: done reading my X inputs

    // px loads for this layer (L0 only) issued first; latency overlaps part-LDS sums
    float pxr[UMAX][3];
#pragma unroll
    for (int u = 0; u < UMAX; ++u) {
        pxr[u][0] = pxr[u][1] = pxr[u][2] = 0.f;
        if (PX) {
            int it = tid + u * NTHR;
            if (it < jlc * MBT) {
                int j2 = it >> 4, b = it & 15;
                const float* pp = pxBase
                    + (size_t)b * (T_ * INTER_ * 3) + (size_t)(jbase + j2) * 3;
                pxr[u][0] = __ldg(pp);
                pxr[u][1] = __ldg(pp + 1);
                pxr[u][2] = __ldg(pp + 2);
            }
        }
    }

    // combine (fully unrolled; compile-time indices -> registers)
    float hreg[UMAX];
    int   hix[UMAX];
#pragma unroll
    for (int u = 0; u < UMAX; ++u) {
        int it = tid + u * NTHR;
        hix[u] = -1;
        if (it < jlc * MBT) {
            int j2 = it >> 4, b = it & 15;
            float s0 = pxr[u][0], s1 = pxr[u][1], s2 = pxr[u][2];
#pragma unroll
            for (int c = 0; c < KC; ++c) {
                const float* pp = part + (c * jlc + j2) * PSTR;
                s0 += pp[b]; s1 += pp[16 + b]; s2 += pp[32 + b];
            }
            int j = jbase + j2;
            float ff1 = tanhf(s0 + bb[j * 3 + 0]);
            float ff2 = tanhf(s1 + bb[j * 3 + 1]);
            float z   = s2 + bb[j * 3 + 2];
            float sg  = 1.0f / (1.0f + __expf(-z));
            hreg[u] = ff1 + sg * (ff2 - ff1);
            hix[u]  = (HOFF + j) * MBT + b;
        }
    }
    CLUSTER_WAIT();           // peer done reading -> safe to write h rows
#pragma unroll
    for (int u = 0; u < UMAX; ++u) {
        if (hix[u] >= 0) {
            X[hix[u]] = hreg[u];
            st_peer(s2u(&X[hix[u]]), peer, hreg[u]);
        }
    }
    __syncthreads();
    CLUSTER_ARRIVE();         // my h writes (incl. peer DSMEM) done
    CLUSTER_WAIT();           // peer's h writes into my X visible
}

// ---------------- main kernel ----------------
#define SM_TOTALF (XROWS * MBT + NTHR * PSTR + (INTER_ + CMD_ + MOTOR_) * 3 \
                   + OUT_ * MOTOR_ + OUT_)
#define SMEM_BYTES (SM_TOTALF * 4)

__global__ void __launch_bounds__(NTHR, 1)
__cluster_dims__(2, 1, 1)
main_kernel(Params P) {
    extern __shared__ float sm[];
    float* X    = sm;                                 // 512*16
    float* part = X + XROWS * MBT;                    // 768*52
    float* bb   = part + NTHR * PSTR;                 // 512*3
    float* fcw  = bb + (INTER_ + CMD_ + MOTOR_) * 3;  // 64*64 [m][o]
    float* fcb  = fcw + OUT_ * MOTOR_;                // 64

    const int tid  = threadIdx.x;
    const int team = blockIdx.x >> 1;
    const int rank = (int)my_rank();
    const int peer = rank ^ 1;
    const int b0   = team * MBT;

    const int jb0 = rank * 135, jl0 = rank ? (INTER_ - 135) : 135;   // 135/134
    const int jb1 = rank * 90,  jl1 = rank ? (CMD_ - 90)   : 90;     // 90/89
    const int jb2 = rank * 32,  jl2 = 32;

    float* bb0 = bb;
    float* bb1 = bb + INTER_ * 3;
    float* bb2 = bb + (INTER_ + CMD_) * 3;
    for (int q = tid; q < INTER_ * 3; q += NTHR) {
        int j = q / 3, g = q - j * 3;
        bb0[q] = (g == 0) ? P.b0[0][j] : (g == 1) ? P.b0[1][j] : (P.b0[2][j] + P.b0[3][j]);
    }
    for (int q = tid; q < CMD_ * 3; q += NTHR) {
        int j = q / 3, g = q - j * 3;
        bb1[q] = (g == 0) ? P.b1[0][j] : (g == 1) ? P.b1[1][j] : (P.b1[2][j] + P.b1[3][j]);
    }
    for (int q = tid; q < MOTOR_ * 3; q += NTHR) {
        int j = q / 3, g = q - j * 3;
        bb2[q] = (g == 0) ? P.b2[0][j] : (g == 1) ? P.b2[1][j] : (P.b2[2][j] + P.b2[3][j]);
    }
    for (int q = tid; q < OUT_ * MOTOR_; q += NTHR) {
        int m = q >> 6, o = q & 63;
        fcw[m * OUT_ + o] = P.fc_w[o * MOTOR_ + m];
    }
    if (tid < OUT_) fcb[tid] = P.fc_b[tid];
    // initial hidden -> X rows [0,512)
    for (int q = tid; q < UNITS_ * MBT; q += NTHR) {
        int u = q >> 4, b = q & 15;
        X[u * MBT + b] = P.hidden[(size_t)(b0 + b) * UNITS_ + u];
    }
    __syncthreads();
    CLUSTER_ARRIVE(); CLUSTER_WAIT();

    for (int t = 0; t < T_; ++t) {
        const float* pxBase = g_px + ((size_t)b0 * T_ + t) * (size_t)(INTER_ * 3);

        do_layer<INTER_, INTER_, KC0, XR_H0, XR_H0, 3, true>(
            g_wq0 + (size_t)DIN_ * INTER_, bb0, X, part, pxBase, jb0, jl0, peer, tid);
        do_layer<CAT1, CMD_, KC1, XR_H0, XR_H1, 2, false>(
            g_wq1, bb1, X, part, (const float*)0, jb1, jl1, peer, tid);
        do_layer<CAT2, MOTOR_, KC2, XR_H1, XR_H2, 1, false>(
            g_wq2, bb2, X, part, (const float*)0, jb2, jl2, peer, tid);

        // output head: this CTA writes its 8 batches (rank half)
        for (int q = tid; q < 8 * OUT_; q += NTHR) {
            int b = rank * 8 + (q >> 6), o = q & 63;
            float acc = fcb[o];
#pragma unroll
            for (int m = 0; m < MOTOR_; ++m)
                acc += X[(XR_H2 + m) * MBT + b] * fcw[m * OUT_ + o];
            P.out[((size_t)(b0 + b) * T_ + t) * OUT_ + o] = acc;
        }
        __syncthreads();
    }

    // final hidden state: X rows [0,512) == concat(h0,h1,h2); my 8 batches
    size_t hoff = (size_t)B_ * T_ * OUT_;
    for (int q = tid; q < 8 * UNITS_; q += NTHR) {
        int b = rank * 8 + (q >> 9);
        int u = q & 511;
        P.out[hoff + (size_t)(b0 + b) * UNITS_ + u] = X[u * MBT + b];
    }
    CLUSTER_ARRIVE();
    CLUSTER_WAIT();
}

// ---------------- launch ----------------
extern "C" void kernel_launch(void* const* d_in, const int* in_sizes, int n_in,
                              void* d_out, int out_size) {
    (void)in_sizes; (void)n_in; (void)out_size;
    Params P;
    P.x      = (const float*)d_in[0];
    P.hidden = (const float*)d_in[1];
    P.mask0  = d_in[2];
    P.mask1  = d_in[3];
    P.mask2  = d_in[4];
    const float** wp[3] = { P.w0, P.w1, P.w2 };
    const float** bp[3] = { P.b0, P.b1, P.b2 };
    int idx = 5;
    for (int l = 0; l < 3; ++l) {
        for (int g = 0; g < 4; ++g) {
            wp[l][g] = (const float*)d_in[idx++];
            bp[l][g] = (const float*)d_in[idx++];
        }
    }
    P.fc_w = (const float*)d_in[idx++];
    P.fc_b = (const float*)d_in[idx++];
    P.out  = (float*)d_out;

    cudaFuncSetAttribute(main_kernel, cudaFuncAttributeMaxDynamicSharedMemorySize,
                         SMEM_BYTES);

    prep_kernel<<<(PTOT_ + 255) / 256, 256>>>(P);
    precomp_kernel<<<BT_ / 16, 640>>>(P.x);
    main_kernel<<<NBLK, NTHR, SMEM_BYTES>>>(P);
}

// round 17
// speedup vs baseline: 1.1485x; 1.1485x over previous
#include <cuda_runtime.h>
#include <math.h>

// ---------------- problem constants ----------------
#define B_      1024
#define T_      256
#define DIN_    128
#define INTER_  269
#define CMD_    179
#define MOTOR_  64
#define OUT_    64
#define UNITS_  512
#define CAT0    397
#define CAT1    448
#define CAT2    243

#define MBT     16                 // batch rows per team (cluster of 2)
#define NBLK    128                // 64 teams x 2
#define NTHR    640                // 20 warps (5/SMSP) -- measured optimum
#define PSTR    52                 // partial slot stride (floats, 16B aligned)

// X rows: [h0 | h1 | h2]; each row = 16 batch floats.
#define XR_H0   0
#define XR_H1   269
#define XR_H2   448
#define XROWS   512

#define KC0     4                  // 135*4=540 tasks (k-range 269)
#define KC1     7                  // 90*7=630
#define KC2     20                 // 32*20=640

#define P0_ (CAT0 * INTER_)
#define P1_ (CAT1 * CMD_)
#define P2_ (CAT2 * MOTOR_)
#define PTOT_ (P0_ + P1_ + P2_)

#define BT_     (B_ * T_)
#define PXN     ((size_t)BT_ * INTER_ * 3)

// ---------------- device scratch ----------------
__device__ __align__(16) float4 g_wq0[P0_];
__device__ __align__(16) float4 g_wq1[P1_];
__device__ __align__(16) float4 g_wq2[P2_];
__device__ float g_px[PXN];          // precomputed x_t @ Wx for layer 0

struct Params {
    const float* x;
    const float* hidden;
    const void*  mask0;
    const void*  mask1;
    const void*  mask2;
    const float* w0[4]; const float* b0[4];   // ff1, ff2, ta, tb
    const float* w1[4]; const float* b1[4];
    const float* w2[4]; const float* b2[4];
    const float* fc_w;  const float* fc_b;
    float* out;
};

// ---------------- mask helper ----------------
__device__ __forceinline__ float mask_val(const void* mp, int mode, int e) {
    if (mode == 0) return ((const unsigned char*)mp)[e] ? 1.0f : 0.0f;
    if (mode == 1) return ((const int*)mp)[e] ? 1.0f : 0.0f;
    return (((const float*)mp)[e] != 0.0f) ? 1.0f : 0.0f;
}

// fast tanh: overflow-safe, ~1e-7 rel precision (vs 1e-3 gate)
__device__ __forceinline__ float ftanh(float x) {
    float ex = __expf(2.0f * fabsf(x));
    return copysignf(1.0f - 2.0f / (ex + 1.0f), x);
}

// ---------------- prep: sniff mask dtype + folded/masked/transposed float4 weights ----------------
__global__ void prep_kernel(Params P) {
    __shared__ int smode[3];
    {
        int w = threadIdx.x >> 5, lane = threadIdx.x & 31;
        if (w < 3) {
            const unsigned char* p = (const unsigned char*)
                (w == 0 ? P.mask0 : (w == 1 ? P.mask1 : P.mask2));
            int nz = 0, gt = 0;
            for (int i = lane; i < 4096; i += 32) {
                unsigned char v = p[i];
                nz += (v != 0);
                gt |= (v > 1);
            }
            nz = __reduce_add_sync(0xffffffffu, nz);
            gt = __reduce_or_sync(0xffffffffu, gt);
            if (lane == 0) smode[w] = gt ? 2 : (nz > 2048 ? 0 : 1);
        }
    }
    __syncthreads();

    int p = blockIdx.x * blockDim.x + threadIdx.x;
    if (p >= PTOT_) return;

    int NH, CATL, local, mode;
    float4* wq;
    const float* const* ws;
    const void* mp;
    if (p < P0_) {
        local = p; NH = INTER_; CATL = CAT0;
        wq = g_wq0; ws = P.w0; mp = P.mask0; mode = smode[0];
    } else if (p < P0_ + P1_) {
        local = p - P0_; NH = CMD_; CATL = CAT1;
        wq = g_wq1; ws = P.w1; mp = P.mask1; mode = smode[1];
    } else {
        local = p - P0_ - P1_; NH = MOTOR_; CATL = CAT2;
        wq = g_wq2; ws = P.w2; mp = P.mask2; mode = smode[2];
    }
    int k = local / NH;
    int j = local - k * NH;
    int we = j * CATL + k;
    float m = mask_val(mp, mode, we);
    float4 v;
    v.x = ws[0][we] * m;
    v.y = ws[1][we] * m;
    v.z = ws[2][we] + ws[3][we];
    v.w = 0.0f;
    wq[local] = v;
}

// ---------------- asm helpers ----------------
__device__ __forceinline__ unsigned long long pack2(float w) {
    unsigned long long r;
    asm("mov.b64 %0, {%1, %1};" : "=l"(r) : "f"(w));
    return r;
}
#define FFMA2(acc, w2, x2) \
    asm("fma.rn.f32x2 %0, %1, %2, %0;" : "+l"(acc) : "l"(w2), "l"(x2))

__device__ __forceinline__ float2 unpack2(unsigned long long v) {
    float2 r;
    asm("mov.b64 {%0, %1}, %2;" : "=f"(r.x), "=f"(r.y) : "l"(v));
    return r;
}
__device__ __forceinline__ unsigned s2u(const void* p) {
    unsigned a;
    asm("{ .reg .u64 t; cvta.to.shared.u64 t, %1; cvt.u32.u64 %0, t; }"
        : "=r"(a) : "l"(p));
    return a;
}
__device__ __forceinline__ void st_peer(unsigned laddr, int peer, float v) {
    unsigned ra;
    asm("mapa.shared::cluster.u32 %0, %1, %2;" : "=r"(ra) : "r"(laddr), "r"(peer));
    asm volatile("st.shared::cluster.f32 [%0], %1;" :: "r"(ra), "f"(v) : "memory");
}
__device__ __forceinline__ unsigned my_rank() {
    unsigned r; asm("mov.u32 %0, %%cluster_ctarank;" : "=r"(r)); return r;
}
#define CLUSTER_ARRIVE() asm volatile("barrier.cluster.arrive.aligned;" ::: "memory")
#define CLUSTER_WAIT()   asm volatile("barrier.cluster.wait.aligned;" ::: "memory")

// ---------------- precompute: px[bt][j][0..2] = sum_k x[bt][k] * wx[g][j][k] ----------------
__global__ void __launch_bounds__(NTHR) precomp_kernel(const float* __restrict__ x) {
    __shared__ float xs[128 * 20];
    const int tid = threadIdx.x;
    const int bt0 = blockIdx.x * 16;

    for (int q = tid; q < 16 * 128; q += NTHR) {
        int m = q >> 7, k = q & 127;
        xs[k * 20 + m] = x[(size_t)(bt0 + m) * DIN_ + k];
    }
    __syncthreads();

    if (tid < 2 * INTER_) {
        int mc = tid / INTER_;
        int jl = tid - mc * INTER_;
        const float4* wp = g_wq0 + jl;      // rows k=0..127 are the x-part
        unsigned long long a[12];
#pragma unroll
        for (int i = 0; i < 12; ++i) a[i] = 0ULL;

        float4 wv = __ldg(wp); wp += INTER_;
#pragma unroll 2
        for (int k = 0; k < 127; ++k) {
            float4 wn = __ldg(wp); wp += INTER_;
            const float* xb = xs + k * 20 + mc * 8;
            ulonglong2 x01 = *(const ulonglong2*)xb;
            ulonglong2 x23 = *(const ulonglong2*)(xb + 4);
            unsigned long long p1 = pack2(wv.x);
            unsigned long long p2 = pack2(wv.y);
            unsigned long long p3 = pack2(wv.z);
            FFMA2(a[0], p1, x01.x); FFMA2(a[1], p1, x01.y);
            FFMA2(a[2], p1, x23.x); FFMA2(a[3], p1, x23.y);
            FFMA2(a[4], p2, x01.x); FFMA2(a[5], p2, x01.y);
            FFMA2(a[6], p2, x23.x); FFMA2(a[7], p2, x23.y);
            FFMA2(a[8], p3, x01.x); FFMA2(a[9], p3, x01.y);
            FFMA2(a[10], p3, x23.x); FFMA2(a[11], p3, x23.y);
            wv = wn;
        }
        {   // k = 127
            const float* xb = xs + 127 * 20 + mc * 8;
            ulonglong2 x01 = *(const ulonglong2*)xb;
            ulonglong2 x23 = *(const ulonglong2*)(xb + 4);
            unsigned long long p1 = pack2(wv.x);
            unsigned long long p2 = pack2(wv.y);
            unsigned long long p3 = pack2(wv.z);
            FFMA2(a[0], p1, x01.x); FFMA2(a[1], p1, x01.y);
            FFMA2(a[2], p1, x23.x); FFMA2(a[3], p1, x23.y);
            FFMA2(a[4], p2, x01.x); FFMA2(a[5], p2, x01.y);
            FFMA2(a[6], p2, x23.x); FFMA2(a[7], p2, x23.y);
            FFMA2(a[8], p3, x01.x); FFMA2(a[9], p3, x01.y);
            FFMA2(a[10], p3, x23.x); FFMA2(a[11], p3, x23.y);
        }
#pragma unroll
        for (int g = 0; g < 3; ++g)
#pragma unroll
            for (int q = 0; q < 4; ++q) {
                float2 v = unpack2(a[g * 4 + q]);
                size_t m0 = (size_t)(bt0 + mc * 8 + 2 * q);
                g_px[(m0 * INTER_ + jl) * 3 + g] = v.x;
                g_px[((m0 + 1) * INTER_ + jl) * 3 + g] = v.y;
            }
    }
}

// ---------------- 24-acc FMA body ----------------
#define FMA_BODY(wv, xp)                                                     \
    do {                                                                     \
        ulonglong2 x01 = *(const ulonglong2*)(xp);                           \
        ulonglong2 x23 = *(const ulonglong2*)((xp) + 4);                     \
        ulonglong2 x45 = *(const ulonglong2*)((xp) + 8);                     \
        ulonglong2 x67 = *(const ulonglong2*)((xp) + 12);                    \
        unsigned long long p1 = pack2((wv).x);                               \
        unsigned long long p2 = pack2((wv).y);                               \
        unsigned long long p3 = pack2((wv).z);                               \
        FFMA2(a[0],  p1, x01.x); FFMA2(a[1],  p1, x01.y);                    \
        FFMA2(a[2],  p1, x23.x); FFMA2(a[3],  p1, x23.y);                    \
        FFMA2(a[4],  p1, x45.x); FFMA2(a[5],  p1, x45.y);                    \
        FFMA2(a[6],  p1, x67.x); FFMA2(a[7],  p1, x67.y);                    \
        FFMA2(a[8],  p2, x01.x); FFMA2(a[9],  p2, x01.y);                    \
        FFMA2(a[10], p2, x23.x); FFMA2(a[11], p2, x23.y);                    \
        FFMA2(a[12], p2, x45.x); FFMA2(a[13], p2, x45.y);                    \
        FFMA2(a[14], p2, x67.x); FFMA2(a[15], p2, x67.y);                    \
        FFMA2(a[16], p3, x01.x); FFMA2(a[17], p3, x01.y);                    \
        FFMA2(a[18], p3, x23.x); FFMA2(a[19], p3, x23.y);                    \
        FFMA2(a[20], p3, x45.x); FFMA2(a[21], p3, x45.y);                    \
        FFMA2(a[22], p3, x67.x); FFMA2(a[23], p3, x67.y);                    \
    } while (0)

// ---------------- one layer ----------------
template <int KRANGE, int NHW, int KC, int XOFF, int HOFF, int UMAX, bool PX>
__device__ __forceinline__ void do_layer(const float4* __restrict__ wq,
                                         const float* __restrict__ bb,
                                         float* __restrict__ X,
                                         float* __restrict__ part,
                                         const float (*pxv)[3],
                                         int jbase, int jlc, int peer, int tid) {
    const int kc = tid / jlc;
    const int jl = tid - kc * jlc;
    if (kc < KC) {
        const int ka = (KRANGE * kc) / KC;
        const int kb = (KRANGE * (kc + 1)) / KC;
        const float4* wp = wq + (size_t)ka * NHW + jbase + jl;
        const float* xp = X + (size_t)(XOFF + ka) * MBT;

        unsigned long long a[24];
#pragma unroll
        for (int i = 0; i < 24; ++i) a[i] = 0ULL;

        float4 wv = __ldg(wp); wp += NHW;
#pragma unroll 2
        for (int k = ka; k < kb - 1; ++k) {
            float4 wn = __ldg(wp); wp += NHW;   // depth-1 rolling prefetch
            FMA_BODY(wv, xp);
            xp += MBT;
            wv = wn;
        }
        FMA_BODY(wv, xp);

        float* pp = part + tid * PSTR;
#pragma unroll
        for (int g = 0; g < 3; ++g)
#pragma unroll
            for (int q = 0; q < 4; ++q) {
                ulonglong2 s;
                s.x = a[g * 8 + q * 2];
                s.y = a[g * 8 + q * 2 + 1];
                *(ulonglong2*)(pp + g * 16 + q * 4) = s;
            }
    }
    __syncthreads();          // partials visible; local X reads done
    CLUSTER_ARRIVE();         // publish: done reading my X inputs

    // combine (fully unrolled; compile-time indices -> registers)
    float hreg[UMAX];
    int   hix[UMAX];
#pragma unroll
    for (int u = 0; u < UMAX; ++u) {
        int it = tid + u * NTHR;
        hix[u] = -1;
        if (it < jlc * MBT) {
            int j2 = it >> 4, b = it & 15;
            float s0, s1, s2;
            if (PX) { s0 = pxv[u][0]; s1 = pxv[u][1]; s2 = pxv[u][2]; }
            else    { s0 = 0.f; s1 = 0.f; s2 = 0.f; }
#pragma unroll
            for (int c = 0; c < KC; ++c) {
                const float* pp = part + (c * jlc + j2) * PSTR;
                s0 += pp[b]; s1 += pp[16 + b]; s2 += pp[32 + b];
            }
            int j = jbase + j2;
            float ff1 = ftanh(s0 + bb[j * 3 + 0]);
            float ff2 = ftanh(s1 + bb[j * 3 + 1]);
            float z   = s2 + bb[j * 3 + 2];
            float sg  = 1.0f / (1.0f + __expf(-z));
            hreg[u] = ff1 + sg * (ff2 - ff1);
            hix[u]  = (HOFF + j) * MBT + b;
        }
    }
    CLUSTER_WAIT();           // peer done reading -> safe to write h rows
#pragma unroll
    for (int u = 0; u < UMAX; ++u) {
        if (hix[u] >= 0) {
            X[hix[u]] = hreg[u];
            st_peer(s2u(&X[hix[u]]), peer, hreg[u]);
        }
    }
    __syncthreads();
    CLUSTER_ARRIVE();         // my h writes (incl. peer DSMEM) done
    CLUSTER_WAIT();           // peer's h writes into my X visible
}

// ---------------- main kernel ----------------
#define SM_TOTALF (XROWS * MBT + NTHR * PSTR + (INTER_ + CMD_ + MOTOR_) * 3 \
                   + OUT_ * MOTOR_ + OUT_)
#define SMEM_BYTES (SM_TOTALF * 4)

__global__ void __launch_bounds__(NTHR, 1)
__cluster_dims__(2, 1, 1)
main_kernel(Params P) {
    extern __shared__ float sm[];
    float* X    = sm;                                 // 512*16
    float* part = X + XROWS * MBT;                    // 640*52
    float* bb   = part + NTHR * PSTR;                 // 512*3
    float* fcw  = bb + (INTER_ + CMD_ + MOTOR_) * 3;  // 64*64 [m][o]
    float* fcb  = fcw + OUT_ * MOTOR_;                // 64

    const int tid  = threadIdx.x;
    const int team = blockIdx.x >> 1;
    const int rank = (int)my_rank();
    const int peer = rank ^ 1;
    const int b0   = team * MBT;

    const int jb0 = rank * 135, jl0 = rank ? (INTER_ - 135) : 135;   // 135/134
    const int jb1 = rank * 90,  jl1 = rank ? (CMD_ - 90)   : 90;     // 90/89
    const int jb2 = rank * 32,  jl2 = 32;

    float* bb0 = bb;
    float* bb1 = bb + INTER_ * 3;
    float* bb2 = bb + (INTER_ + CMD_) * 3;
    for (int q = tid; q < INTER_ * 3; q += NTHR) {
        int j = q / 3, g = q - j * 3;
        bb0[q] = (g == 0) ? P.b0[0][j] : (g == 1) ? P.b0[1][j] : (P.b0[2][j] + P.b0[3][j]);
    }
    for (int q = tid; q < CMD_ * 3; q += NTHR) {
        int j = q / 3, g = q - j * 3;
        bb1[q] = (g == 0) ? P.b1[0][j] : (g == 1) ? P.b1[1][j] : (P.b1[2][j] + P.b1[3][j]);
    }
    for (int q = tid; q < MOTOR_ * 3; q += NTHR) {
        int j = q / 3, g = q - j * 3;
        bb2[q] = (g == 0) ? P.b2[0][j] : (g == 1) ? P.b2[1][j] : (P.b2[2][j] + P.b2[3][j]);
    }
    for (int q = tid; q < OUT_ * MOTOR_; q += NTHR) {
        int m = q >> 6, o = q & 63;
        fcw[m * OUT_ + o] = P.fc_w[o * MOTOR_ + m];
    }
    if (tid < OUT_) fcb[tid] = P.fc_b[tid];
    // initial hidden -> X rows [0,512)
    for (int q = tid; q < UNITS_ * MBT; q += NTHR) {
        int u = q >> 4, b = q & 15;
        X[u * MBT + b] = P.hidden[(size_t)(b0 + b) * UNITS_ + u];
    }
    __syncthreads();
    CLUSTER_ARRIVE(); CLUSTER_WAIT();

    for (int t = 0; t < T_; ++t) {
        // prefetch this step's px (layer-0 combine init) into registers
        float pxv[4][3];
#pragma unroll
        for (int u = 0; u < 4; ++u) {
            int it = tid + u * NTHR;
            pxv[u][0] = pxv[u][1] = pxv[u][2] = 0.f;
            if (it < jl0 * MBT) {
                int j2 = it >> 4, b = it & 15;
                const float* pp = g_px
                    + ((size_t)(b0 + b) * T_ + t) * (INTER_ * 3) + (jb0 + j2) * 3;
                pxv[u][0] = pp[0]; pxv[u][1] = pp[1]; pxv[u][2] = pp[2];
            }
        }

        do_layer<INTER_, INTER_, KC0, XR_H0, XR_H0, 4, true>(
            g_wq0 + (size_t)DIN_ * INTER_, bb0, X, part, pxv, jb0, jl0, peer, tid);
        do_layer<CAT1, CMD_, KC1, XR_H0, XR_H1, 3, false>(
            g_wq1, bb1, X, part, pxv, jb1, jl1, peer, tid);
        do_layer<CAT2, MOTOR_, KC2, XR_H1, XR_H2, 1, false>(
            g_wq2, bb2, X, part, pxv, jb2, jl2, peer, tid);

        // output head: this CTA writes its 8 batches (rank half)
        for (int q = tid; q < 8 * OUT_; q += NTHR) {
            int b = rank * 8 + (q >> 6), o = q & 63;
            float acc = fcb[o];
#pragma unroll
            for (int m = 0; m < MOTOR_; ++m)
                acc += X[(XR_H2 + m) * MBT + b] * fcw[m * OUT_ + o];
            P.out[((size_t)(b0 + b) * T_ + t) * OUT_ + o] = acc;
        }
        __syncthreads();
    }

    // final hidden state: X rows [0,512) == concat(h0,h1,h2); my 8 batches
    size_t hoff = (size_t)B_ * T_ * OUT_;
    for (int q = tid; q < 8 * UNITS_; q += NTHR) {
        int b = rank * 8 + (q >> 9);
        int u = q & 511;
        P.out[hoff + (size_t)(b0 + b) * UNITS_ + u] = X[u * MBT + b];
    }
    CLUSTER_ARRIVE();
    CLUSTER_WAIT();
}

// ---------------- launch ----------------
extern "C" void kernel_launch(void* const* d_in, const int* in_sizes, int n_in,
                              void* d_out, int out_size) {
    (void)in_sizes; (void)n_in; (void)out_size;
    Params P;
    P.x      = (const float*)d_in[0];
    P.hidden = (const float*)d_in[1];
    P.mask0  = d_in[2];
    P.mask1  = d_in[3];
    P.mask2  = d_in[4];
    const float** wp[3] = { P.w0, P.w1, P.w2 };
    const float** bp[3] = { P.b0, P.b1, P.b2 };
    int idx = 5;
    for (int l = 0; l < 3; ++l) {
        for (int g = 0; g < 4; ++g) {
            wp[l][g] = (const float*)d_in[idx++];
            bp[l][g] = (const float*)d_in[idx++];
        }
    }
    P.fc_w = (const float*)d_in[idx++];
    P.fc_b = (const float*)d_in[idx++];
    P.out  = (float*)d_out;

    cudaFuncSetAttribute(main_kernel, cudaFuncAttributeMaxDynamicSharedMemorySize,
                         SMEM_BYTES);

    prep_kernel<<<(PTOT_ + 255) / 256, 256>>>(P);
    precomp_kernel<<<BT_ / 16, NTHR>>>(P.x);
    main_kernel<<<NBLK, NTHR, SMEM_BYTES>>>(P);
}